// round 16
// baseline (speedup 1.0000x reference)
#include <cuda_runtime.h>
#include <cuda_fp16.h>
#include <math.h>

#define SEQL   2048
#define BATCH  64
#define INDIM  512
#define HID    512
#define NCTA   128
#define NTHR   512

// smem byte offsets
#define XA_OFF   0            // 32 rows x 1040 B (x tile, sub-CTA A) [canonical W @ setup]
#define XB_OFF   33280
#define HA_OFF   66560
#define HB_OFF   99840
#define FIH_OFF  133120       // Wih frags: [nt*2+kh][chunk16][lane] uint4 = 32768
#define FHH_OFF  165888       // Whh frags
#define PA_OFF   198656       // float [2][32][18] = 4608
#define PB_OFF   203264
#define BIAS_OFF 207872       // 16 floats
#define F0_OFF   207936       // 2 unsigned
#define SMEM_TOTAL 207952

__device__ unsigned g_flagsA[NCTA];                               // monotonic across runs
__device__ unsigned g_flagsB[NCTA];
__device__ __align__(16) __half g_xh[(size_t)SEQL * BATCH * 512]; // fp16 x
__device__ __align__(16) __half g_hA[2][32 * 512];                // ping-pong fp16 h (A)
__device__ __align__(16) __half g_hB[2][32 * 512];                // (B)

__device__ __forceinline__ float sigm(float x){
    return __fdividef(1.0f, 1.0f + __expf(-x));
}
__device__ __forceinline__ float ftanh(float x){
    float e = __expf(-2.0f * x);
    return __fdividef(1.0f - e, 1.0f + e);
}

// ---- cp.async ----
__device__ __forceinline__ void cp16(unsigned s, const void* g){
    asm volatile("cp.async.cg.shared.global [%0], [%1], 16;" :: "r"(s), "l"(g) : "memory");
}
__device__ __forceinline__ void cp_commit(){ asm volatile("cp.async.commit_group;" ::: "memory"); }
__device__ __forceinline__ void cp_wait0(){ asm volatile("cp.async.wait_group 0;" ::: "memory"); }
__device__ __forceinline__ void cp_wait1(){ asm volatile("cp.async.wait_group 1;" ::: "memory"); }

// ---- flags ----
__device__ __forceinline__ void st_rel(unsigned* p, unsigned v){
    asm volatile("st.release.gpu.u32 [%0], %1;" :: "l"(p), "r"(v) : "memory");
}
__device__ __forceinline__ unsigned ld_acq(unsigned* p){
    unsigned v; asm volatile("ld.acquire.gpu.u32 %0, [%1];" : "=r"(v) : "l"(p) : "memory");
    return v;
}

// ---- tensor-core primitives ----
__device__ __forceinline__ void ldsm4(unsigned a, unsigned &r0, unsigned &r1,
                                      unsigned &r2, unsigned &r3){
    asm volatile("ldmatrix.sync.aligned.m8n8.x4.shared.b16 {%0,%1,%2,%3}, [%4];"
                 : "=r"(r0), "=r"(r1), "=r"(r2), "=r"(r3) : "r"(a));
}
__device__ __forceinline__ void ldsm2(unsigned a, unsigned &r0, unsigned &r1){
    asm volatile("ldmatrix.sync.aligned.m8n8.x2.shared.b16 {%0,%1}, [%2];"
                 : "=r"(r0), "=r"(r1) : "r"(a));
}
__device__ __forceinline__ void lds128(unsigned a, unsigned &r0, unsigned &r1,
                                       unsigned &r2, unsigned &r3){
    asm volatile("ld.shared.v4.u32 {%0,%1,%2,%3}, [%4];"
                 : "=r"(r0), "=r"(r1), "=r"(r2), "=r"(r3) : "r"(a));
}
__device__ __forceinline__ void sts128(unsigned a, unsigned r0, unsigned r1,
                                       unsigned r2, unsigned r3){
    asm volatile("st.shared.v4.b32 [%0], {%1,%2,%3,%4};"
                 :: "r"(a), "r"(r0), "r"(r1), "r"(r2), "r"(r3) : "memory");
}
__device__ __forceinline__ void mmaf16(float &c0, float &c1, float &c2, float &c3,
                                       unsigned a0, unsigned a1, unsigned a2, unsigned a3,
                                       unsigned b0, unsigned b1){
    asm volatile("mma.sync.aligned.m16n8k16.row.col.f32.f16.f16.f32 "
                 "{%0,%1,%2,%3}, {%4,%5,%6,%7}, {%8,%9}, {%0,%1,%2,%3};"
                 : "+f"(c0), "+f"(c1), "+f"(c2), "+f"(c3)
                 : "r"(a0), "r"(a1), "r"(a2), "r"(a3), "r"(b0), "r"(b1));
}

// ============ kernel 1: x fp32 -> fp16 ============
__global__ void __launch_bounds__(256, 4)
xconv(const float* __restrict__ in)
{
    int t = blockIdx.x;
    const float4* src = (const float4*)(in + (size_t)t * BATCH * INDIM);
    __half2* dst = (__half2*)(g_xh + (size_t)t * BATCH * 512);
    for (int i = threadIdx.x; i < BATCH * INDIM / 4; i += 256) {
        float4 v = src[i];
        dst[i * 2]     = __floats2half2_rn(v.x, v.y);
        dst[i * 2 + 1] = __floats2half2_rn(v.z, v.w);
    }
}

// ============ kernel 2: persistent LSTM, two independent sub-CTAs ============
__global__ void __launch_bounds__(NTHR, 1)
lstm_persistent(const float* __restrict__ Wih,
                const float* __restrict__ Whh,
                const float* __restrict__ bih,
                const float* __restrict__ bhh,
                float* __restrict__ out)
{
    extern __shared__ char sm[];
    const unsigned sb = (unsigned)__cvta_generic_to_shared(sm);
    float* bias = (float*)(sm + BIAS_OFF);
    unsigned* sF0 = (unsigned*)(sm + F0_OFF);

    const int tid = threadIdx.x;
    const int cta = blockIdx.x;
    const int hc0 = cta * 4;

    if (tid == 0) { sF0[0] = g_flagsA[cta]; sF0[1] = g_flagsB[cta]; }

    // ---- canonical weights (fp16 hi/lo) at sm+0 (66560 B, spans XA+XB) ----
    for (int i = tid; i < 16 * 512; i += NTHR) {
        int r = i >> 9, k = i & 511;
        int grow = (r >> 2) * 512 + hc0 + (r & 3);
        float w = Wih[(size_t)grow * INDIM + k];
        __half h = __float2half(w);
        *(__half*)(sm + 0*16640 + r*1040 + k*2) = h;
        *(__half*)(sm + 1*16640 + r*1040 + k*2) = __float2half(w - __half2float(h));
        w = Whh[(size_t)grow * HID + k];
        h = __float2half(w);
        *(__half*)(sm + 2*16640 + r*1040 + k*2) = h;
        *(__half*)(sm + 3*16640 + r*1040 + k*2) = __float2half(w - __half2float(h));
    }
    if (tid < 16) {
        int grow = (tid >> 2) * 512 + hc0 + (tid & 3);
        bias[tid] = bih[grow] + bhh[grow];
    }
    __syncthreads();

    const int wid = tid >> 5, lane = tid & 31;

    // ---- pre-swizzle weight b-fragments (warps 0-3, one (nt,kh) combo each) ----
    if (wid < 4) {
        int ntS = wid >> 1, khS = wid & 1;
        unsigned cb = sb + (unsigned)((ntS*8 + (lane & 7))*1040
                                      + ((lane >> 3) & 1)*16 + khS*512);
        unsigned fi = sb + FIH_OFF + (unsigned)((ntS*2 + khS)*8192 + lane*16);
        unsigned fh = sb + FHH_OFF + (unsigned)((ntS*2 + khS)*8192 + lane*16);
#pragma unroll
        for (int c = 0; c < 16; ++c) {
            unsigned h0,h1,l0,l1;
            ldsm2(cb + c*32,           h0, h1);
            ldsm2(cb + 16640 + c*32,   l0, l1);
            sts128(fi + c*512, h0, h1, l0, l1);
            ldsm2(cb + 2*16640 + c*32, h0, h1);
            ldsm2(cb + 3*16640 + c*32, l0, l1);
            sts128(fh + c*512, h0, h1, l0, l1);
        }
    }
    __syncthreads();                                   // frags ready; canonical dead

    // ---- stage x(0) for both groups ----
    for (int j = 0; j < 8; ++j) {
        int i = tid + j * NTHR;                        // 0..4095 over 64 rows
        int row = i >> 6, u = i & 63;
        unsigned dst = (row < 32) ? (unsigned)(XA_OFF + row*1040 + u*16)
                                  : (unsigned)(XB_OFF + (row-32)*1040 + u*16);
        cp16(sb + dst, g_xh + row*512 + u*8);
    }
    cp_commit(); cp_wait0();
    __syncthreads();

    // ================= sub-CTA split =================
    const int grp  = tid >> 8;                         // 0 = rows 0-31, 1 = rows 32-63
    const int gtid = tid & 255;
    const int gwid = gtid >> 5;                        // warp within group 0..7
    const int barid = 1 + grp;

    const unsigned F0 = sF0[grp];
    unsigned* flags = grp ? g_flagsB : g_flagsA;
    const unsigned xoff = grp ? XB_OFF : XA_OFF;
    const unsigned hoff = grp ? HB_OFF : HA_OFF;
    float* part = (float*)(sm + (grp ? PB_OFF : PA_OFF));

    // warp identity within group: mt(2) x nt(2) x kh(2)
    const int mt = gwid & 1, nt = (gwid >> 1) & 1, kh = gwid >> 2;

    const unsigned aX = sb + xoff + (unsigned)((mt*16 + (lane & 15))*1040
                                               + (lane >> 4)*16 + kh*512);
    const unsigned aH = aX + (hoff - xoff);
    const unsigned fIh = sb + FIH_OFF + (unsigned)((nt*2 + kh)*8192 + lane*16);
    const unsigned fHh = sb + FHH_OFF + (unsigned)((nt*2 + kh)*8192 + lane*16);

    const int brow = mt*16 + (lane >> 2);
    const int pcol = nt*8 + (lane & 3)*2;
    float* pp = part + (kh*32 + brow)*18 + pcol;

    const int ub = gtid >> 2, uhcl = gtid & 3;         // update identity (gtid<128)
    unsigned* fpoll = &flags[(gwid << 4) + (lane & 15)];

    float cst = 0.0f;

#define BARG() asm volatile("bar.sync %0, 256;" :: "r"(barid) : "memory")

    for (int t = 0; t < SEQL; ++t) {
        if (t > 0) {
            // stage h(t-1) — flags verified at end of previous iteration
            const __half* hs = grp ? g_hB[(t - 1) & 1] : g_hA[(t - 1) & 1];
#pragma unroll
            for (int j = 0; j < 8; ++j) {
                int i = gtid + j * 256;                // 0..2047
                int row = i >> 6, u = i & 63;
                cp16(sb + hoff + (unsigned)(row*1040 + u*16), hs + row*512 + u*8);
            }
            cp_commit();
            cp_wait1();                                // x(t) landed; h still flying
            BARG();
        }

        float c0 = 0.f, c1 = 0.f, c2 = 0.f, c3 = 0.f;

        // ---- x-MMA: 16 chunks (K-half 256) ----
#pragma unroll 4
        for (int c = 0; c < 16; ++c) {
            unsigned a0,a1,a2,a3, b0,b1,b2,b3;
            ldsm4(aX + c*32, a0,a1,a2,a3);
            lds128(fIh + c*512, b0,b1,b2,b3);
            mmaf16(c0,c1,c2,c3, a0,a1,a2,a3, b0,b1);
            mmaf16(c0,c1,c2,c3, a0,a1,a2,a3, b2,b3);
        }

        if (t > 0) {
            cp_wait0(); BARG();                        // h(t-1) landed
#pragma unroll 4
            for (int c = 0; c < 16; ++c) {
                unsigned a0,a1,a2,a3, b0,b1,b2,b3;
                ldsm4(aH + c*32, a0,a1,a2,a3);
                lds128(fHh + c*512, b0,b1,b2,b3);
                mmaf16(c0,c1,c2,c3, a0,a1,a2,a3, b0,b1);
                mmaf16(c0,c1,c2,c3, a0,a1,a2,a3, b2,b3);
            }
        }

        // ---- K-half partials ----
        pp[0] = c0; pp[1] = c1; pp[8*18] = c2; pp[8*18 + 1] = c3;
        BARG();

        if (gtid < 128) {                              // update: one (b, hcl) per thread
            float sv[4];
#pragma unroll
            for (int g = 0; g < 4; ++g) {
                int r = g*4 + uhcl;
                sv[g] = bias[r] + part[ub*18 + r] + part[(32 + ub)*18 + r];
            }
            float ig = sigm(sv[0]), fg = sigm(sv[1]);
            float gv = ftanh(sv[2]), og = sigm(sv[3]);
            float cn = fmaf(fg, cst, ig * gv);
            cst = cn;
            float hn = og * ftanh(cn);

            if (grp) g_hB[t & 1][ub*512 + hc0 + uhcl] = __float2half(hn);
            else     g_hA[t & 1][ub*512 + hc0 + uhcl] = __float2half(hn);
            int gb = grp*32 + ub;
            out[(size_t)t * BATCH * HID + (size_t)gb * HID + hc0 + uhcl] = hn;
            if (t == SEQL - 1)
                out[(size_t)SEQL * BATCH * HID + (size_t)gb * HID + hc0 + uhcl] = hn;
        }
        BARG();
        if (gtid == 0) st_rel(&flags[cta], F0 + (unsigned)(t + 1));

        if (t + 1 < SEQL) {
            // prefetch x(t+1) (flight overlaps the poll below + next stage)
            const __half* gx = g_xh + (size_t)(t + 1) * BATCH * 512 + grp * 32 * 512;
#pragma unroll
            for (int j = 0; j < 8; ++j) {
                int i = gtid + j * 256;
                int row = i >> 6, u = i & 63;
                cp16(sb + xoff + (unsigned)(row*1040 + u*16), gx + row*512 + u*8);
            }
            cp_commit();

            // poll: all 8 warps, 16 flags each (own release just posted)
            unsigned tgt = F0 + (unsigned)(t + 1);
            for (;;) {
                unsigned f = ld_acq(fpoll);
                if (__all_sync(0xffffffffu, (int)(f - tgt) >= 0)) break;
            }
            BARG();
        }
    }

    // c_n
    if (gtid < 128)
        out[(size_t)SEQL * BATCH * HID + (size_t)BATCH * HID
            + (size_t)(grp*32 + ub) * HID + hc0 + uhcl] = cst;
#undef BARG
}

extern "C" void kernel_launch(void* const* d_in, const int* in_sizes, int n_in,
                              void* d_out, int out_size)
{
    const float* input = (const float*)d_in[0];
    const float* Wih   = (const float*)d_in[1];
    const float* Whh   = (const float*)d_in[2];
    const float* bih   = (const float*)d_in[3];
    const float* bhh   = (const float*)d_in[4];
    float* out = (float*)d_out;

    static int configured = 0;
    if (!configured) {
        cudaFuncSetAttribute(lstm_persistent,
                             cudaFuncAttributeMaxDynamicSharedMemorySize, SMEM_TOTAL);
        configured = 1;
    }

    xconv<<<SEQL, 256>>>(input);
    lstm_persistent<<<NCTA, NTHR, SMEM_TOTAL>>>(Wih, Whh, bih, bhh, out);
}

// round 17
// speedup vs baseline: 2.4961x; 2.4961x over previous
#include <cuda_runtime.h>
#include <cuda_fp16.h>
#include <math.h>

#define SEQL   2048
#define BATCH  64
#define INDIM  512
#define HID    512
#define NCTA   128
#define NTHR   512

// smem byte offsets
#define XA_OFF   0            // 32 rows x 1040 B (x tile, group A)  [canonical W at setup]
#define XB_OFF   33280        // x tile, group B
#define HA_OFF   66560        // h tile, group A
#define HB_OFF   99840        // h tile, group B
#define FIH_OFF  133120       // Wih frags: [nt*4+kq][chunk][lane] uint4 = 32768
#define FHH_OFF  165888       // Whh frags
#define PA_OFF   198656       // float [4][32][18] = 9216
#define PB_OFF   207872
#define BIAS_OFF 217088       // 16 floats
#define F0_OFF   217152       // 2 unsigned
#define SMEM_TOTAL 217168

__device__ unsigned g_flagsA[NCTA];                               // monotonic across runs
__device__ unsigned g_flagsB[NCTA];
__device__ __align__(16) __half g_xh[(size_t)SEQL * BATCH * 512]; // fp16 x
__device__ __align__(16) __half g_hA[2][32 * 512];                // ping-pong fp16 h, group A
__device__ __align__(16) __half g_hB[2][32 * 512];                // group B

__device__ __forceinline__ float sigm(float x){
    return __fdividef(1.0f, 1.0f + __expf(-x));
}
__device__ __forceinline__ float ftanh(float x){
    float e = __expf(-2.0f * x);
    return __fdividef(1.0f - e, 1.0f + e);
}

// ---- cp.async ----
__device__ __forceinline__ void cp16(unsigned s, const void* g){
    asm volatile("cp.async.cg.shared.global [%0], [%1], 16;" :: "r"(s), "l"(g) : "memory");
}
__device__ __forceinline__ void cp_commit(){ asm volatile("cp.async.commit_group;" ::: "memory"); }
template<int N> __device__ __forceinline__ void cp_wait(){
    asm volatile("cp.async.wait_group %0;" :: "n"(N) : "memory");
}

// ---- flags ----
__device__ __forceinline__ void st_rel(unsigned* p, unsigned v){
    asm volatile("st.release.gpu.u32 [%0], %1;" :: "l"(p), "r"(v) : "memory");
}
__device__ __forceinline__ unsigned ld_acq(unsigned* p){
    unsigned v; asm volatile("ld.acquire.gpu.u32 %0, [%1];" : "=r"(v) : "l"(p) : "memory");
    return v;
}

// ---- tensor-core primitives ----
__device__ __forceinline__ void ldsm4(unsigned a, unsigned &r0, unsigned &r1,
                                      unsigned &r2, unsigned &r3){
    asm volatile("ldmatrix.sync.aligned.m8n8.x4.shared.b16 {%0,%1,%2,%3}, [%4];"
                 : "=r"(r0), "=r"(r1), "=r"(r2), "=r"(r3) : "r"(a));
}
__device__ __forceinline__ void ldsm2(unsigned a, unsigned &r0, unsigned &r1){
    asm volatile("ldmatrix.sync.aligned.m8n8.x2.shared.b16 {%0,%1}, [%2];"
                 : "=r"(r0), "=r"(r1) : "r"(a));
}
__device__ __forceinline__ void lds128(unsigned a, unsigned &r0, unsigned &r1,
                                       unsigned &r2, unsigned &r3){
    asm volatile("ld.shared.v4.u32 {%0,%1,%2,%3}, [%4];"
                 : "=r"(r0), "=r"(r1), "=r"(r2), "=r"(r3) : "r"(a));
}
__device__ __forceinline__ void sts128(unsigned a, unsigned r0, unsigned r1,
                                       unsigned r2, unsigned r3){
    asm volatile("st.shared.v4.b32 [%0], {%1,%2,%3,%4};"
                 :: "r"(a), "r"(r0), "r"(r1), "r"(r2), "r"(r3) : "memory");
}
__device__ __forceinline__ void mmaf16(float &c0, float &c1, float &c2, float &c3,
                                       unsigned a0, unsigned a1, unsigned a2, unsigned a3,
                                       unsigned b0, unsigned b1){
    asm volatile("mma.sync.aligned.m16n8k16.row.col.f32.f16.f16.f32 "
                 "{%0,%1,%2,%3}, {%4,%5,%6,%7}, {%8,%9}, {%0,%1,%2,%3};"
                 : "+f"(c0), "+f"(c1), "+f"(c2), "+f"(c3)
                 : "r"(a0), "r"(a1), "r"(a2), "r"(a3), "r"(b0), "r"(b1));
}

// ============ kernel 1: x fp32 -> fp16 ============
__global__ void __launch_bounds__(256, 4)
xconv(const float* __restrict__ in)
{
    int t = blockIdx.x;
    const float4* src = (const float4*)(in + (size_t)t * BATCH * INDIM);
    __half2* dst = (__half2*)(g_xh + (size_t)t * BATCH * 512);
    for (int i = threadIdx.x; i < BATCH * INDIM / 4; i += 256) {
        float4 v = src[i];
        dst[i * 2]     = __floats2half2_rn(v.x, v.y);
        dst[i * 2 + 1] = __floats2half2_rn(v.z, v.w);
    }
}

// ============ kernel 2: fused persistent LSTM, 2-group pipeline (R15 + reorder) ============
__global__ void __launch_bounds__(NTHR, 1)
lstm_persistent(const float* __restrict__ Wih,
                const float* __restrict__ Whh,
                const float* __restrict__ bih,
                const float* __restrict__ bhh,
                float* __restrict__ out)
{
    extern __shared__ char sm[];
    const unsigned sb = (unsigned)__cvta_generic_to_shared(sm);
    float* partA = (float*)(sm + PA_OFF);
    float* partB = (float*)(sm + PB_OFF);
    float* bias  = (float*)(sm + BIAS_OFF);
    unsigned* sF0 = (unsigned*)(sm + F0_OFF);

    const int tid = threadIdx.x;
    const int cta = blockIdx.x;
    const int hc0 = cta * 4;

    if (tid == 0) { sF0[0] = g_flagsA[cta]; sF0[1] = g_flagsB[cta]; }

    // ---- canonical weights (fp16 hi/lo) into XA/XB region temporarily ----
    for (int i = tid; i < 16 * 512; i += NTHR) {
        int r = i >> 9, k = i & 511;
        int grow = (r >> 2) * 512 + hc0 + (r & 3);
        float w = Wih[(size_t)grow * INDIM + k];
        __half h = __float2half(w);
        *(__half*)(sm + XA_OFF + 0*16640 + r*1040 + k*2) = h;
        *(__half*)(sm + XA_OFF + 1*16640 + r*1040 + k*2) = __float2half(w - __half2float(h));
        w = Whh[(size_t)grow * HID + k];
        h = __float2half(w);
        *(__half*)(sm + XA_OFF + 2*16640 + r*1040 + k*2) = h;
        *(__half*)(sm + XA_OFF + 3*16640 + r*1040 + k*2) = __float2half(w - __half2float(h));
    }
    if (tid < 16) {
        int grow = (tid >> 2) * 512 + hc0 + (tid & 3);
        bias[tid] = bih[grow] + bhh[grow];
    }
    __syncthreads();

    const int wid = tid >> 5, lane = tid & 31;
    // warp identity: mt(2 x 16-row batch tiles) x nt(2 x 8-row gate tiles) x kq(4 K-quarters)
    const int mt = wid & 1, nt = (wid >> 1) & 1, kq = wid >> 2;

    // ---- pre-swizzle weight b-fragments (warps 0-7: (ntS, kqS)) ----
    if (wid < 8) {
        int ntS = wid >> 2, kqS = wid & 3;
        unsigned cb = sb + XA_OFF + (unsigned)((ntS*8 + (lane & 7))*1040
                                               + ((lane >> 3) & 1)*16 + kqS*256);
        unsigned fi = sb + FIH_OFF + (unsigned)(((ntS*4 + kqS)*8)*512 + lane*16);
        unsigned fh = sb + FHH_OFF + (unsigned)(((ntS*4 + kqS)*8)*512 + lane*16);
#pragma unroll
        for (int c = 0; c < 8; ++c) {
            unsigned h0,h1,l0,l1;
            ldsm2(cb + c*32,           h0, h1);
            ldsm2(cb + 16640 + c*32,   l0, l1);
            sts128(fi + c*512, h0, h1, l0, l1);
            ldsm2(cb + 2*16640 + c*32, h0, h1);
            ldsm2(cb + 3*16640 + c*32, l0, l1);
            sts128(fh + c*512, h0, h1, l0, l1);
        }
    }
    __syncthreads();                                   // frags ready; canonical dead

    // ---- stage xA(0), xB(0) and drain fully ----
    for (int j = 0; j < 4; ++j) {
        int i = tid + j * NTHR;
        int row = i >> 6, u = i & 63;
        cp16(sb + (unsigned)(XA_OFF + row*1040 + u*16), g_xh + row*512 + u*8);
    }
    for (int j = 0; j < 4; ++j) {
        int i = tid + j * NTHR;
        int row = i >> 6, u = i & 63;
        cp16(sb + (unsigned)(XB_OFF + row*1040 + u*16), g_xh + (32 + row)*512 + u*8);
    }
    cp_commit(); cp_wait<0>();
    __syncthreads();
    const unsigned F0A = sF0[0], F0B = sF0[1];

    // per-warp constant addresses
    const unsigned aXA = sb + (unsigned)(XA_OFF + (mt*16 + (lane & 15))*1040
                                         + (lane >> 4)*16 + kq*256);
    const unsigned aXB = aXA + (XB_OFF - XA_OFF);
    const unsigned aHA = aXA + (HA_OFF - XA_OFF);
    const unsigned aHB = aXA + (HB_OFF - XA_OFF);
    const unsigned fIh = sb + FIH_OFF + (unsigned)(((nt*4 + kq)*8)*512 + lane*16);
    const unsigned fHh = sb + FHH_OFF + (unsigned)(((nt*4 + kq)*8)*512 + lane*16);

    const int brow = mt*16 + (lane >> 2);              // group-local batch row of c0/c1
    const int pcol = nt*8 + (lane & 3)*2;
    float* ppA = partA + (kq*32 + brow)*18 + pcol;
    float* ppB = partB + (kq*32 + brow)*18 + pcol;

    const int ub = (tid & 127) >> 2, uhcl = tid & 3;   // update identity within group

    float cst = 0.0f;                                  // cstA for tid<128, cstB for 128..255

    for (int t = 0; t < SEQL; ++t) {
        // ================= A phase =================
        cp_wait<2>(); __syncthreads();                 // xA(t) landed (hA, xB still flying)

        float c0 = 0.f, c1 = 0.f, c2 = 0.f, c3 = 0.f;
#pragma unroll
        for (int c = 0; c < 8; ++c) {
            unsigned a0,a1,a2,a3, b0,b1,b2,b3;
            ldsm4(aXA + c*32, a0,a1,a2,a3);
            lds128(fIh + c*512, b0,b1,b2,b3);
            mmaf16(c0,c1,c2,c3, a0,a1,a2,a3, b0,b1);
            mmaf16(c0,c1,c2,c3, a0,a1,a2,a3, b2,b3);
        }
        if (t > 0) {
            cp_wait<1>(); __syncthreads();             // hA(t-1) landed (xB(t) stays)
#pragma unroll
            for (int c = 0; c < 8; ++c) {
                unsigned a0,a1,a2,a3, b0,b1,b2,b3;
                ldsm4(aHA + c*32, a0,a1,a2,a3);
                lds128(fHh + c*512, b0,b1,b2,b3);
                mmaf16(c0,c1,c2,c3, a0,a1,a2,a3, b0,b1);
                mmaf16(c0,c1,c2,c3, a0,a1,a2,a3, b2,b3);
            }
        }
        ppA[0] = c0; ppA[1] = c1; ppA[8*18] = c2; ppA[8*18 + 1] = c3;
        __syncthreads();

        float hnA = 0.f;
        if (tid < 128) {                               // update A (h publish only)
            float sv[4];
#pragma unroll
            for (int g = 0; g < 4; ++g) {
                int r = g*4 + uhcl;
                float s = bias[r];
#pragma unroll
                for (int q = 0; q < 4; ++q) s += partA[(q*32 + ub)*18 + r];
                sv[g] = s;
            }
            float ig = sigm(sv[0]), fg = sigm(sv[1]);
            float gv = ftanh(sv[2]), og = sigm(sv[3]);
            float cn = fmaf(fg, cst, ig * gv);
            cst = cn;
            hnA = og * ftanh(cn);
            g_hA[t & 1][ub*512 + hc0 + uhcl] = __float2half(hnA);
        } else if (wid >= 8) {                         // poll B(t) (trivially true at t=0)
            unsigned tgt = F0B + (unsigned)t;
            unsigned* fp = &g_flagsB[((wid - 8) << 4) + (lane & 15)];
            for (;;) {
                unsigned f = ld_acq(fp);
                if (__all_sync(0xffffffffu, (int)(f - tgt) >= 0)) break;
            }
        }
        __syncthreads();                               // hA stores done + poll B(t) verified
        if (tid == 0) st_rel(&g_flagsA[cta], F0A + (unsigned)(t + 1));

        // stage hB(t-1) NOW — maximal flight before B-phase h-MMA
        if (t > 0) {
            const __half* hs = g_hB[(t - 1) & 1];
#pragma unroll
            for (int j = 0; j < 4; ++j) {
                int i = tid + j * NTHR;                // 0..2047
                int row = i >> 6, u = i & 63;
                cp16(sb + (unsigned)(HB_OFF + row*1040 + u*16), hs + row*512 + u*8);
            }
        }
        cp_commit();                                   // (empty at t=0)

        if (t + 1 < SEQL) {                            // prefetch xA(t+1)
            const __half* gx = g_xh + (size_t)(t + 1) * BATCH * 512;
#pragma unroll
            for (int j = 0; j < 4; ++j) {
                int i = tid + j * NTHR;
                int row = i >> 6, u = i & 63;
                cp16(sb + (unsigned)(XA_OFF + row*1040 + u*16), gx + row*512 + u*8);
            }
        }
        cp_commit();                                   // (empty at last step)

        if (tid < 128) {                               // out stores — off critical path
            out[(size_t)t * BATCH * HID + (size_t)ub * HID + hc0 + uhcl] = hnA;
            if (t == SEQL - 1)
                out[(size_t)SEQL * BATCH * HID + (size_t)ub * HID + hc0 + uhcl] = hnA;
        }

        // ================= B phase =================
        cp_wait<2>(); __syncthreads();                 // xB(t) landed (hB, xA(t+1) flying)

        c0 = 0.f; c1 = 0.f; c2 = 0.f; c3 = 0.f;
#pragma unroll
        for (int c = 0; c < 8; ++c) {
            unsigned a0,a1,a2,a3, b0,b1,b2,b3;
            ldsm4(aXB + c*32, a0,a1,a2,a3);
            lds128(fIh + c*512, b0,b1,b2,b3);
            mmaf16(c0,c1,c2,c3, a0,a1,a2,a3, b0,b1);
            mmaf16(c0,c1,c2,c3, a0,a1,a2,a3, b2,b3);
        }
        if (t > 0) {
            cp_wait<1>(); __syncthreads();             // hB(t-1) landed (xA(t+1) stays)
#pragma unroll
            for (int c = 0; c < 8; ++c) {
                unsigned a0,a1,a2,a3, b0,b1,b2,b3;
                ldsm4(aHB + c*32, a0,a1,a2,a3);
                lds128(fHh + c*512, b0,b1,b2,b3);
                mmaf16(c0,c1,c2,c3, a0,a1,a2,a3, b0,b1);
                mmaf16(c0,c1,c2,c3, a0,a1,a2,a3, b2,b3);
            }
        }
        ppB[0] = c0; ppB[1] = c1; ppB[8*18] = c2; ppB[8*18 + 1] = c3;
        __syncthreads();

        float hnB = 0.f;
        if (tid >= 128 && tid < 256) {                 // update B
            float sv[4];
#pragma unroll
            for (int g = 0; g < 4; ++g) {
                int r = g*4 + uhcl;
                float s = bias[r];
#pragma unroll
                for (int q = 0; q < 4; ++q) s += partB[(q*32 + ub)*18 + r];
                sv[g] = s;
            }
            float ig = sigm(sv[0]), fg = sigm(sv[1]);
            float gv = ftanh(sv[2]), og = sigm(sv[3]);
            float cn = fmaf(fg, cst, ig * gv);
            cst = cn;
            hnB = og * ftanh(cn);
            g_hB[t & 1][ub*512 + hc0 + uhcl] = __float2half(hnB);
        } else if (wid >= 8) {                         // poll A(t+1)
            if (t + 1 < SEQL) {
                unsigned tgt = F0A + (unsigned)(t + 1);
                unsigned* fp = &g_flagsA[((wid - 8) << 4) + (lane & 15)];
                for (;;) {
                    unsigned f = ld_acq(fp);
                    if (__all_sync(0xffffffffu, (int)(f - tgt) >= 0)) break;
                }
            }
        }
        __syncthreads();                               // hB stores done + poll A(t+1) verified
        if (tid == 0) st_rel(&g_flagsB[cta], F0B + (unsigned)(t + 1));

        // stage hA(t) NOW — verified by poll A(t+1)
        if (t + 1 < SEQL) {
            const __half* hs = g_hA[t & 1];
#pragma unroll
            for (int j = 0; j < 4; ++j) {
                int i = tid + j * NTHR;
                int row = i >> 6, u = i & 63;
                cp16(sb + (unsigned)(HA_OFF + row*1040 + u*16), hs + row*512 + u*8);
            }
        }
        cp_commit();                                   // (empty at last step)

        if (t + 1 < SEQL) {                            // prefetch xB(t+1)
            const __half* gx = g_xh + (size_t)(t + 1) * BATCH * 512;
#pragma unroll
            for (int j = 0; j < 4; ++j) {
                int i = tid + j * NTHR;
                int row = i >> 6, u = i & 63;
                cp16(sb + (unsigned)(XB_OFF + row*1040 + u*16), gx + (32 + row)*512 + u*8);
            }
        }
        cp_commit();                                   // (empty at last step)

        if (tid >= 128 && tid < 256) {                 // out stores B — off critical path
            int gb = 32 + ub;
            out[(size_t)t * BATCH * HID + (size_t)gb * HID + hc0 + uhcl] = hnB;
            if (t == SEQL - 1)
                out[(size_t)SEQL * BATCH * HID + (size_t)gb * HID + hc0 + uhcl] = hnB;
        }
    }

    // c_n
    if (tid < 128)
        out[(size_t)SEQL * BATCH * HID + (size_t)BATCH * HID
            + (size_t)ub * HID + hc0 + uhcl] = cst;
    else if (tid < 256)
        out[(size_t)SEQL * BATCH * HID + (size_t)BATCH * HID
            + (size_t)(32 + ub) * HID + hc0 + uhcl] = cst;
}

extern "C" void kernel_launch(void* const* d_in, const int* in_sizes, int n_in,
                              void* d_out, int out_size)
{
    const float* input = (const float*)d_in[0];
    const float* Wih   = (const float*)d_in[1];
    const float* Whh   = (const float*)d_in[2];
    const float* bih   = (const float*)d_in[3];
    const float* bhh   = (const float*)d_in[4];
    float* out = (float*)d_out;

    static int configured = 0;
    if (!configured) {
        cudaFuncSetAttribute(lstm_persistent,
                             cudaFuncAttributeMaxDynamicSharedMemorySize, SMEM_TOTAL);
        configured = 1;
    }

    xconv<<<SEQL, 256>>>(input);
    lstm_persistent<<<NCTA, NTHR, SMEM_TOTAL>>>(Wih, Whh, bih, bhh, out);
}